// round 5
// baseline (speedup 1.0000x reference)
#include <cuda_runtime.h>
#include <cstdint>

// Shapes (fixed): B=4, T=2048, C=2048, nH=16, hd=128
// Output = concat(y [B,T,C], new_k [B,nH,T,hd], new_v [B,nH,T,hd])

#define C_DIM   2048
#define T_DIM   2048
#define B_DIM   4
#define NH      16
#define HD      128
#define MTOT    (B_DIM * T_DIM)         // 8192
#define YELEMS  (B_DIM * T_DIM * C_DIM) // 16777216

__device__ uint32_t g_xtf[YELEMS];
__device__ uint32_t g_wqkvtf[3 * C_DIM * C_DIM];
__device__ uint32_t g_wouttf[C_DIM * C_DIM];
__device__ uint32_t g_qbuf[YELEMS];             // q [B,nH,T,hd], tf32
__device__ uint32_t g_ybuf[YELEMS];             // attn out [B,T,C], tf32

__device__ __forceinline__ uint32_t f2tf(float f) {
    uint32_t u;
    asm("cvt.rna.tf32.f32 %0, %1;" : "=r"(u) : "f"(f));
    return u;
}

__device__ __forceinline__ void mma_tf32(float* c, const uint32_t* a,
                                         const uint32_t* b) {
    asm volatile(
        "mma.sync.aligned.m16n8k8.row.col.f32.tf32.tf32.f32 "
        "{%0,%1,%2,%3},{%4,%5,%6,%7},{%8,%9},{%0,%1,%2,%3};"
        : "+f"(c[0]), "+f"(c[1]), "+f"(c[2]), "+f"(c[3])
        : "r"(a[0]), "r"(a[1]), "r"(a[2]), "r"(a[3]), "r"(b[0]), "r"(b[1]));
}

__device__ __forceinline__ void cpasync16(uint32_t smem_addr, const void* g) {
    asm volatile("cp.async.cg.shared.global [%0], [%1], 16;"
                 :: "r"(smem_addr), "l"(g));
}

// ---------------------------------------------------------------------------
__global__ __launch_bounds__(256) void cvt_tf32_kernel(
    const float4* __restrict__ src, uint4* __restrict__ dst, int n4)
{
    for (int i = blockIdx.x * blockDim.x + threadIdx.x; i < n4;
         i += gridDim.x * blockDim.x) {
        float4 v = src[i];
        uint4 u;
        u.x = f2tf(v.x); u.y = f2tf(v.y); u.z = f2tf(v.z); u.w = f2tf(v.w);
        dst[i] = u;
    }
}

// ---------------------------------------------------------------------------
// TF32 GEMM: 256x128x32 tile, 512 threads (16 warps, 4x4), warp tile 64x32.
// 3-stage cp.async ring, one __syncthreads per k-iter.
// smem layout (dynamic, words): A stages 3 x 256 x 36, then B stages 3 x 128 x 36.
// ---------------------------------------------------------------------------
#define BM 256
#define BN 128
#define BK 32
#define LDW 36
#define AW  (BM * LDW)            // 9216 words per A stage
#define BW  (BN * LDW)            // 4608 words per B stage
#define GEMM_SMEM ((3 * (AW + BW)) * 4)   // 165888 bytes

template <int MODE>
__global__ __launch_bounds__(512, 1) void mma_gemm(
    const uint32_t* __restrict__ A,   // [M,2048] tf32
    const uint32_t* __restrict__ W,   // [N,2048] tf32
    const float* __restrict__ bias,
    float* __restrict__ out0,         // MODE0: k ; MODE1: y
    float* __restrict__ out1)         // MODE0: v
{
    const int K = C_DIM;
    extern __shared__ uint32_t smem[];

    const int tid  = threadIdx.x;
    const int lane = tid & 31;
    const int wid  = tid >> 5;        // 0..15
    const int wm   = wid >> 2;        // 0..3
    const int wn   = wid & 3;         // 0..3
    const int m0   = blockIdx.y * BM;
    const int n0   = blockIdx.x * BN;

    const int crow = tid >> 3;        // 0..63
    const int ckq  = (tid & 7) << 2;  // 0..28

    float acc[4][4][4];
#pragma unroll
    for (int i = 0; i < 4; i++)
#pragma unroll
        for (int j = 0; j < 4; j++)
#pragma unroll
            for (int c = 0; c < 4; c++) acc[i][j][c] = 0.0f;

    // stage issue helper (A: 4 rows/thread, B: 2 rows/thread)
    auto issue_stage = [&](int s, int k0) {
        uint32_t* as = smem + s * AW;
        uint32_t* bs = smem + 3 * AW + s * BW;
#pragma unroll
        for (int r = 0; r < 4; r++) {
            int row = crow + r * 64;
            cpasync16((uint32_t)__cvta_generic_to_shared(&as[row * LDW + ckq]),
                      &A[(size_t)(m0 + row) * K + k0 + ckq]);
        }
#pragma unroll
        for (int r = 0; r < 2; r++) {
            int row = crow + r * 64;
            cpasync16((uint32_t)__cvta_generic_to_shared(&bs[row * LDW + ckq]),
                      &W[(size_t)(n0 + row) * K + k0 + ckq]);
        }
        asm volatile("cp.async.commit_group;");
    };

    const int NIT = K / BK;           // 64
    issue_stage(0, 0);
    issue_stage(1, BK);

    int buf = 0;
    for (int i = 0; i < NIT; i++) {
        if (i + 1 < NIT) {
            asm volatile("cp.async.wait_group 1;");
        } else {
            asm volatile("cp.async.wait_group 0;");
        }
        __syncthreads();
        if (i + 2 < NIT) {
            int s = (i + 2) % 3;
            issue_stage(s, (i + 2) * BK);
        }

        const uint32_t* as = smem + buf * AW;
        const uint32_t* bs = smem + 3 * AW + buf * BW;
#pragma unroll
        for (int ks = 0; ks < 4; ks++) {
            const int kb = ks * 8;
            uint32_t af[4][4], bf[4][2];
#pragma unroll
            for (int am = 0; am < 4; am++) {
                int mr = wm * 64 + am * 16 + (lane >> 2);
                int kc = kb + (lane & 3);
                af[am][0] = as[mr * LDW + kc];
                af[am][1] = as[(mr + 8) * LDW + kc];
                af[am][2] = as[mr * LDW + kc + 4];
                af[am][3] = as[(mr + 8) * LDW + kc + 4];
            }
#pragma unroll
            for (int an = 0; an < 4; an++) {
                int nr = wn * 32 + an * 8 + (lane >> 2);
                int kc = kb + (lane & 3);
                bf[an][0] = bs[nr * LDW + kc];
                bf[an][1] = bs[nr * LDW + kc + 4];
            }
#pragma unroll
            for (int am = 0; am < 4; am++)
#pragma unroll
                for (int an = 0; an < 4; an++)
                    mma_tf32(acc[am][an], af[am], bf[an]);
        }
        buf = (buf + 1) % 3;
    }

    // ---- epilogue ----
    if (MODE == 0) {
        const int seg = n0 >> 11;           // 0=q, 1=k, 2=v
        const int hh  = (n0 & 2047) >> 7;
#pragma unroll
        for (int am = 0; am < 4; am++) {
#pragma unroll
            for (int cp = 0; cp < 2; cp++) {
                int row = wm * 64 + am * 16 + (lane >> 2) + cp * 8;
                int m = m0 + row;
                int b_ = m >> 11;
                int t  = m & 2047;
                size_t base = (((size_t)(b_ * NH + hh) * T_DIM) + t) * HD;
                if (seg == 0) {
                    uint32_t* dstrow = g_qbuf + base;
#pragma unroll
                    for (int an = 0; an < 4; an++) {
                        int cl = wn * 32 + an * 8 + (lane & 3) * 2;
                        uint2 v;
                        v.x = f2tf(acc[am][an][cp * 2 + 0] + bias[n0 + cl]);
                        v.y = f2tf(acc[am][an][cp * 2 + 1] + bias[n0 + cl + 1]);
                        *reinterpret_cast<uint2*>(&dstrow[cl]) = v;
                    }
                } else {
                    float* dstrow = ((seg == 1) ? out0 : out1) + base;
#pragma unroll
                    for (int an = 0; an < 4; an++) {
                        int cl = wn * 32 + an * 8 + (lane & 3) * 2;
                        float2 v;
                        v.x = acc[am][an][cp * 2 + 0] + bias[n0 + cl];
                        v.y = acc[am][an][cp * 2 + 1] + bias[n0 + cl + 1];
                        *reinterpret_cast<float2*>(&dstrow[cl]) = v;
                    }
                }
            }
        }
    } else {
#pragma unroll
        for (int am = 0; am < 4; am++) {
#pragma unroll
            for (int cp = 0; cp < 2; cp++) {
                int row = wm * 64 + am * 16 + (lane >> 2) + cp * 8;
                int m = m0 + row;
                float* dstrow = out0 + (size_t)m * C_DIM + n0;
#pragma unroll
                for (int an = 0; an < 4; an++) {
                    int cl = wn * 32 + an * 8 + (lane & 3) * 2;
                    float2 v;
                    v.x = acc[am][an][cp * 2 + 0] + bias[n0 + cl];
                    v.y = acc[am][an][cp * 2 + 1] + bias[n0 + cl + 1];
                    *reinterpret_cast<float2*>(&dstrow[cl]) = v;
                }
            }
        }
    }
}

// ---------------------------------------------------------------------------
// TF32 MMA flash attention (unchanged from R4)
// ---------------------------------------------------------------------------
#define AQ_LD 132
#define AV_LD 136
#define AP_LD 68

__global__ __launch_bounds__(256, 1) void attn_mma_kernel(
    const float* __restrict__ Kt, const float* __restrict__ Vt)
{
    extern __shared__ uint32_t sm[];
    uint32_t* Qs = sm;
    uint32_t* Ks = Qs + 128 * AQ_LD;
    uint32_t* Vs = Ks + 64 * AQ_LD;
    uint32_t* Ps = Vs + 64 * AV_LD;

    const int tid  = threadIdx.x;
    const int lane = tid & 31;
    const int w    = tid >> 5;
    const int iq   = blockIdx.x;
    const int bh   = blockIdx.y;
    const int b    = bh >> 4;
    const int h    = bh & 15;

    const uint32_t* qp = g_qbuf + ((size_t)bh * T_DIM + iq * 128) * HD;
    const float* kp = Kt + (size_t)bh * T_DIM * HD;
    const float* vp = Vt + (size_t)bh * T_DIM * HD;

#pragma unroll
    for (int r = 0; r < 16; r++) {
        int idx = tid + r * 256;
        int row = idx >> 5;
        int c   = (idx & 31) << 2;
        *reinterpret_cast<uint4*>(&Qs[row * AQ_LD + c]) =
            *reinterpret_cast<const uint4*>(&qp[row * HD + c]);
    }

    const int r0 = lane >> 2;
    float m_i[2] = {-1e30f, -1e30f};
    float l_i[2] = {0.0f, 0.0f};
    float oacc[16][4];
#pragma unroll
    for (int na = 0; na < 16; na++)
#pragma unroll
        for (int c = 0; c < 4; c++) oacc[na][c] = 0.0f;

    const float scale = 0.08838834764831843f;
    const int jmax = 2 * iq + 1;

    for (int j = 0; j <= jmax; j++) {
        __syncthreads();
        const float* kb = kp + (size_t)j * 64 * HD;
        const float* vb = vp + (size_t)j * 64 * HD;
#pragma unroll
        for (int r = 0; r < 8; r++) {
            int idx = tid + r * 256;
            int row = idx >> 5;
            int c   = (idx & 31) << 2;
            float4 kv = *reinterpret_cast<const float4*>(&kb[row * HD + c]);
            Ks[row * AQ_LD + c + 0] = f2tf(kv.x);
            Ks[row * AQ_LD + c + 1] = f2tf(kv.y);
            Ks[row * AQ_LD + c + 2] = f2tf(kv.z);
            Ks[row * AQ_LD + c + 3] = f2tf(kv.w);
            float4 vv = *reinterpret_cast<const float4*>(&vb[row * HD + c]);
            Vs[row * AV_LD + c + 0] = f2tf(vv.x);
            Vs[row * AV_LD + c + 1] = f2tf(vv.y);
            Vs[row * AV_LD + c + 2] = f2tf(vv.z);
            Vs[row * AV_LD + c + 3] = f2tf(vv.w);
        }
        __syncthreads();

        float sacc[8][4];
#pragma unroll
        for (int na = 0; na < 8; na++)
#pragma unroll
            for (int c = 0; c < 4; c++) sacc[na][c] = 0.0f;

#pragma unroll
        for (int ks = 0; ks < 16; ks++) {
            int kc = ks * 8 + (lane & 3);
            uint32_t af[4];
            int mr = w * 16 + r0;
            af[0] = Qs[mr * AQ_LD + kc];
            af[1] = Qs[(mr + 8) * AQ_LD + kc];
            af[2] = Qs[mr * AQ_LD + kc + 4];
            af[3] = Qs[(mr + 8) * AQ_LD + kc + 4];
#pragma unroll
            for (int na = 0; na < 8; na++) {
                uint32_t bf[2];
                int nr = na * 8 + r0;
                bf[0] = Ks[nr * AQ_LD + kc];
                bf[1] = Ks[nr * AQ_LD + kc + 4];
                mma_tf32(sacc[na], af, bf);
            }
        }

#pragma unroll
        for (int na = 0; na < 8; na++)
#pragma unroll
            for (int c = 0; c < 4; c++) sacc[na][c] *= scale;
        if (j >= 2 * iq) {
            int qrow0 = iq * 128 + w * 16 + r0;
#pragma unroll
            for (int na = 0; na < 8; na++) {
                int col = j * 64 + na * 8 + 2 * (lane & 3);
                if (col > qrow0)     sacc[na][0] = -1e30f;
                if (col + 1 > qrow0) sacc[na][1] = -1e30f;
                if (col > qrow0 + 8)     sacc[na][2] = -1e30f;
                if (col + 1 > qrow0 + 8) sacc[na][3] = -1e30f;
            }
        }

        float mt[2] = {-1e30f, -1e30f};
#pragma unroll
        for (int na = 0; na < 8; na++) {
            mt[0] = fmaxf(mt[0], fmaxf(sacc[na][0], sacc[na][1]));
            mt[1] = fmaxf(mt[1], fmaxf(sacc[na][2], sacc[na][3]));
        }
#pragma unroll
        for (int off = 1; off <= 2; off <<= 1) {
            mt[0] = fmaxf(mt[0], __shfl_xor_sync(0xffffffffu, mt[0], off));
            mt[1] = fmaxf(mt[1], __shfl_xor_sync(0xffffffffu, mt[1], off));
        }
        float mnew0 = fmaxf(m_i[0], mt[0]);
        float mnew1 = fmaxf(m_i[1], mt[1]);
        float alpha0 = __expf(m_i[0] - mnew0);
        float alpha1 = __expf(m_i[1] - mnew1);
        m_i[0] = mnew0; m_i[1] = mnew1;

        float sum0 = 0.0f, sum1 = 0.0f;
#pragma unroll
        for (int na = 0; na < 8; na++) {
            float p0 = __expf(sacc[na][0] - mnew0);
            float p1 = __expf(sacc[na][1] - mnew0);
            float p2 = __expf(sacc[na][2] - mnew1);
            float p3 = __expf(sacc[na][3] - mnew1);
            sum0 += p0 + p1; sum1 += p2 + p3;
            int prow = w * 16 + r0;
            int pcol = na * 8 + 2 * (lane & 3);
            uint2 pv0 = make_uint2(f2tf(p0), f2tf(p1));
            uint2 pv1 = make_uint2(f2tf(p2), f2tf(p3));
            *reinterpret_cast<uint2*>(&Ps[prow * AP_LD + pcol]) = pv0;
            *reinterpret_cast<uint2*>(&Ps[(prow + 8) * AP_LD + pcol]) = pv1;
        }
#pragma unroll
        for (int off = 1; off <= 2; off <<= 1) {
            sum0 += __shfl_xor_sync(0xffffffffu, sum0, off);
            sum1 += __shfl_xor_sync(0xffffffffu, sum1, off);
        }
        l_i[0] = l_i[0] * alpha0 + sum0;
        l_i[1] = l_i[1] * alpha1 + sum1;
#pragma unroll
        for (int na = 0; na < 16; na++) {
            oacc[na][0] *= alpha0; oacc[na][1] *= alpha0;
            oacc[na][2] *= alpha1; oacc[na][3] *= alpha1;
        }

        __syncwarp();

#pragma unroll
        for (int ks = 0; ks < 8; ks++) {
            int kc = ks * 8 + (lane & 3);
            uint32_t af[4];
            int mr = w * 16 + r0;
            af[0] = Ps[mr * AP_LD + kc];
            af[1] = Ps[(mr + 8) * AP_LD + kc];
            af[2] = Ps[mr * AP_LD + kc + 4];
            af[3] = Ps[(mr + 8) * AP_LD + kc + 4];
#pragma unroll
            for (int na = 0; na < 16; na++) {
                uint32_t bf[2];
                bf[0] = Vs[kc * AV_LD + na * 8 + r0];
                bf[1] = Vs[(kc + 4) * AV_LD + na * 8 + r0];
                mma_tf32(oacc[na], af, bf);
            }
        }
        __syncwarp();
    }

    float inv0 = 1.0f / l_i[0];
    float inv1 = 1.0f / l_i[1];
    int t0 = iq * 128 + w * 16 + r0;
    int t1 = t0 + 8;
    uint32_t* dst0 = g_ybuf + ((size_t)(b * T_DIM + t0) * C_DIM) + h * HD;
    uint32_t* dst1 = g_ybuf + ((size_t)(b * T_DIM + t1) * C_DIM) + h * HD;
#pragma unroll
    for (int na = 0; na < 16; na++) {
        int col = na * 8 + 2 * (lane & 3);
        uint2 v0, v1;
        v0.x = f2tf(oacc[na][0] * inv0); v0.y = f2tf(oacc[na][1] * inv0);
        v1.x = f2tf(oacc[na][2] * inv1); v1.y = f2tf(oacc[na][3] * inv1);
        *reinterpret_cast<uint2*>(&dst0[col]) = v0;
        *reinterpret_cast<uint2*>(&dst1[col]) = v1;
    }
}

// ---------------------------------------------------------------------------
extern "C" void kernel_launch(void* const* d_in, const int* in_sizes, int n_in,
                              void* d_out, int out_size)
{
    const float* x    = (const float*)d_in[0];
    const float* Wqkv = (const float*)d_in[1];
    const float* bqkv = (const float*)d_in[2];
    const float* Wout = (const float*)d_in[3];
    const float* bout = (const float*)d_in[4];

    float* y    = (float*)d_out;
    float* kout = y + YELEMS;
    float* vout = y + 2 * YELEMS;

    uint32_t *xtf, *wqkvtf, *wouttf, *ybuf;
    cudaGetSymbolAddress((void**)&xtf,    g_xtf);
    cudaGetSymbolAddress((void**)&wqkvtf, g_wqkvtf);
    cudaGetSymbolAddress((void**)&wouttf, g_wouttf);
    cudaGetSymbolAddress((void**)&ybuf,   g_ybuf);

    const int attn_smem =
        (128 * AQ_LD + 64 * AQ_LD + 64 * AV_LD + 128 * AP_LD) * 4;  // 171008
    cudaFuncSetAttribute(attn_mma_kernel,
                         cudaFuncAttributeMaxDynamicSharedMemorySize, attn_smem);
    cudaFuncSetAttribute(mma_gemm<0>,
                         cudaFuncAttributeMaxDynamicSharedMemorySize, GEMM_SMEM);
    cudaFuncSetAttribute(mma_gemm<1>,
                         cudaFuncAttributeMaxDynamicSharedMemorySize, GEMM_SMEM);

    // 0) tf32 pre-conversion of GEMM inputs
    cvt_tf32_kernel<<<2048, 256>>>((const float4*)x, (uint4*)xtf, YELEMS / 4);
    cvt_tf32_kernel<<<2048, 256>>>((const float4*)Wqkv, (uint4*)wqkvtf,
                                   3 * C_DIM * C_DIM / 4);
    cvt_tf32_kernel<<<1024, 256>>>((const float4*)Wout, (uint4*)wouttf,
                                   C_DIM * C_DIM / 4);

    // 1) QKV projection (256x128 tf32 MMA, 3-stage cp.async) + head scatter
    mma_gemm<0><<<dim3(3 * C_DIM / BN, MTOT / BM), 512, GEMM_SMEM>>>(
        xtf, wqkvtf, bqkv, kout, vout);

    // 2) causal flash attention (tf32 MMA) -> g_ybuf (tf32)
    attn_mma_kernel<<<dim3(T_DIM / 128, B_DIM * NH), 256, attn_smem>>>(
        kout, vout);

    // 3) output projection -> y
    mma_gemm<1><<<dim3(C_DIM / BN, MTOT / BM), 512, GEMM_SMEM>>>(
        ybuf, wouttf, bout, y, nullptr);
}

// round 8
// speedup vs baseline: 2.0550x; 2.0550x over previous
#include <cuda_runtime.h>
#include <cuda_fp16.h>
#include <cstdint>

// Shapes (fixed): B=4, T=2048, C=2048, nH=16, hd=128
// Output = concat(y [B,T,C], new_k [B,nH,T,hd], new_v [B,nH,T,hd])

#define C_DIM   2048
#define T_DIM   2048
#define B_DIM   4
#define NH      16
#define HD      128
#define MTOT    (B_DIM * T_DIM)         // 8192
#define YELEMS  (B_DIM * T_DIM * C_DIM) // 16777216

// fp16 staging buffers
__device__ __half g_xh[YELEMS];
__device__ __half g_wqkvh[3 * C_DIM * C_DIM];
__device__ __half g_wouth[C_DIM * C_DIM];
__device__ __half g_qh[YELEMS];     // q [B,nH,T,hd]
__device__ __half g_kh[YELEMS];     // k [B,nH,T,hd] (fp16 copy for attn)
__device__ __half g_vh[YELEMS];     // v [B,nH,T,hd]
__device__ __half g_yh[YELEMS];     // attn out [B,T,C]

__device__ __forceinline__ uint32_t pkh(float lo, float hi) {
    __half2 h = __floats2half2_rn(lo, hi);
    return *reinterpret_cast<uint32_t*>(&h);
}

__device__ __forceinline__ void mma_f16(float* c, const uint32_t* a,
                                        const uint32_t* b) {
    asm volatile(
        "mma.sync.aligned.m16n8k16.row.col.f32.f16.f16.f32 "
        "{%0,%1,%2,%3},{%4,%5,%6,%7},{%8,%9},{%0,%1,%2,%3};"
        : "+f"(c[0]), "+f"(c[1]), "+f"(c[2]), "+f"(c[3])
        : "r"(a[0]), "r"(a[1]), "r"(a[2]), "r"(a[3]), "r"(b[0]), "r"(b[1]));
}

__device__ __forceinline__ void ldsm4(uint32_t& r0, uint32_t& r1,
                                      uint32_t& r2, uint32_t& r3, uint32_t a) {
    asm volatile("ldmatrix.sync.aligned.m8n8.x4.shared.b16 {%0,%1,%2,%3},[%4];"
                 : "=r"(r0), "=r"(r1), "=r"(r2), "=r"(r3) : "r"(a));
}
__device__ __forceinline__ void ldsm4t(uint32_t& r0, uint32_t& r1,
                                       uint32_t& r2, uint32_t& r3, uint32_t a) {
    asm volatile(
        "ldmatrix.sync.aligned.m8n8.x4.trans.shared.b16 {%0,%1,%2,%3},[%4];"
        : "=r"(r0), "=r"(r1), "=r"(r2), "=r"(r3) : "r"(a));
}

__device__ __forceinline__ void cpasync16(uint32_t smem_addr, const void* g) {
    asm volatile("cp.async.cg.shared.global [%0], [%1], 16;"
                 :: "r"(smem_addr), "l"(g));
}

// ---------------------------------------------------------------------------
// fp32 -> fp16 conversion (vectorized, grid-stride)
// ---------------------------------------------------------------------------
__global__ __launch_bounds__(256) void cvt_f16_kernel(
    const float4* __restrict__ src, uint2* __restrict__ dst, int n4)
{
    for (int i = blockIdx.x * blockDim.x + threadIdx.x; i < n4;
         i += gridDim.x * blockDim.x) {
        float4 v = src[i];
        uint2 o;
        o.x = pkh(v.x, v.y);
        o.y = pkh(v.z, v.w);
        dst[i] = o;
    }
}

// ---------------------------------------------------------------------------
// FP16 GEMM: C[m,n] = sum_k A[m,k]*W[n,k] + bias[n]
// 128x128x32 tile, 256 threads (8 warps 2x4), warp 64x32, m16n8k16.
// 3-stage cp.async ring, one barrier/iter, 2 CTAs/SM.
// ---------------------------------------------------------------------------
#define BM 128
#define BN 128
#define BK 32
#define LDH 40
#define AWH (BM * LDH)                 // 5120 halves / stage
#define GEMM_SMEM (6 * AWH * 2)        // 61440 bytes (3 stages x (A+B))

template <int MODE>
__global__ __launch_bounds__(256, 2) void mma_gemm(
    const __half* __restrict__ A,     // [M,2048]
    const __half* __restrict__ W,     // [N,2048]
    const float* __restrict__ bias,
    float* __restrict__ out0,         // MODE0: k ; MODE1: y
    float* __restrict__ out1)         // MODE0: v
{
    const int K = C_DIM;
    extern __shared__ __half hsm[];

    const int tid  = threadIdx.x;
    const int lane = tid & 31;
    const int wid  = tid >> 5;
    const int wm   = wid >> 2;        // 0..1
    const int wn   = wid & 3;         // 0..3
    const int m0   = blockIdx.y * BM;
    const int n0   = blockIdx.x * BN;

    const int g   = lane >> 3;        // ldmatrix group
    const int l8  = lane & 7;

    const int crow = tid >> 2;        // 0..63
    const int ckq  = (tid & 3) << 3;  // 0,8,16,24 halves

    float acc[4][4][4];
#pragma unroll
    for (int i = 0; i < 4; i++)
#pragma unroll
        for (int j = 0; j < 4; j++)
#pragma unroll
            for (int c = 0; c < 4; c++) acc[i][j][c] = 0.0f;

    auto issue_stage = [&](int s, int k0) {
        __half* as = hsm + s * AWH;
        __half* bs = hsm + 3 * AWH + s * AWH;
#pragma unroll
        for (int r = 0; r < 2; r++) {
            int row = crow + r * 64;
            cpasync16((uint32_t)__cvta_generic_to_shared(&as[row * LDH + ckq]),
                      &A[(size_t)(m0 + row) * K + k0 + ckq]);
            cpasync16((uint32_t)__cvta_generic_to_shared(&bs[row * LDH + ckq]),
                      &W[(size_t)(n0 + row) * K + k0 + ckq]);
        }
        asm volatile("cp.async.commit_group;");
    };

    const int NIT = K / BK;           // 64
    issue_stage(0, 0);
    issue_stage(1, BK);

    int buf = 0;
    for (int i = 0; i < NIT; i++) {
        if (i + 1 < NIT) {
            asm volatile("cp.async.wait_group 1;");
        } else {
            asm volatile("cp.async.wait_group 0;");
        }
        __syncthreads();
        if (i + 2 < NIT) issue_stage((i + 2) % 3, (i + 2) * BK);

        const __half* as = hsm + buf * AWH;
        const __half* bs = hsm + 3 * AWH + buf * AWH;
#pragma unroll
        for (int kb = 0; kb < BK; kb += 16) {
            uint32_t af[4][4], bf[2][4];
#pragma unroll
            for (int am = 0; am < 4; am++) {
                int row = wm * 64 + am * 16 + (g & 1) * 8 + l8;
                int col = kb + (g >> 1) * 8;
                ldsm4(af[am][0], af[am][1], af[am][2], af[am][3],
                      (uint32_t)__cvta_generic_to_shared(&as[row * LDH + col]));
            }
#pragma unroll
            for (int ap = 0; ap < 2; ap++) {
                int row = wn * 32 + ap * 16 + (g >> 1) * 8 + l8;
                int col = kb + (g & 1) * 8;
                ldsm4(bf[ap][0], bf[ap][1], bf[ap][2], bf[ap][3],
                      (uint32_t)__cvta_generic_to_shared(&bs[row * LDH + col]));
            }
#pragma unroll
            for (int am = 0; am < 4; am++)
#pragma unroll
                for (int an = 0; an < 4; an++)
                    mma_f16(acc[am][an], af[am], &bf[an >> 1][(an & 1) * 2]);
        }
        buf = (buf + 1) % 3;
    }

    // ---- epilogue ----
    if (MODE == 0) {
        const int seg = n0 >> 11;           // 0=q, 1=k, 2=v
        const int hh  = (n0 & 2047) >> 7;
#pragma unroll
        for (int am = 0; am < 4; am++) {
#pragma unroll
            for (int cp = 0; cp < 2; cp++) {
                int row = wm * 64 + am * 16 + (lane >> 2) + cp * 8;
                int m = m0 + row;
                int b_ = m >> 11;
                int t  = m & 2047;
                size_t base = (((size_t)(b_ * NH + hh) * T_DIM) + t) * HD;
                if (seg == 0) {
                    __half* dstrow = g_qh + base;
#pragma unroll
                    for (int an = 0; an < 4; an++) {
                        int cl = wn * 32 + an * 8 + (lane & 3) * 2;
                        uint32_t v = pkh(acc[am][an][cp * 2 + 0] + bias[n0 + cl],
                                         acc[am][an][cp * 2 + 1] + bias[n0 + cl + 1]);
                        *reinterpret_cast<uint32_t*>(&dstrow[cl]) = v;
                    }
                } else {
                    float* dstrow = ((seg == 1) ? out0 : out1) + base;
                    __half* hrow  = ((seg == 1) ? g_kh : g_vh) + base;
#pragma unroll
                    for (int an = 0; an < 4; an++) {
                        int cl = wn * 32 + an * 8 + (lane & 3) * 2;
                        float2 v;
                        v.x = acc[am][an][cp * 2 + 0] + bias[n0 + cl];
                        v.y = acc[am][an][cp * 2 + 1] + bias[n0 + cl + 1];
                        *reinterpret_cast<float2*>(&dstrow[cl]) = v;
                        *reinterpret_cast<uint32_t*>(&hrow[cl]) = pkh(v.x, v.y);
                    }
                }
            }
        }
    } else {
#pragma unroll
        for (int am = 0; am < 4; am++) {
#pragma unroll
            for (int cp = 0; cp < 2; cp++) {
                int row = wm * 64 + am * 16 + (lane >> 2) + cp * 8;
                int m = m0 + row;
                float* dstrow = out0 + (size_t)m * C_DIM + n0;
#pragma unroll
                for (int an = 0; an < 4; an++) {
                    int cl = wn * 32 + an * 8 + (lane & 3) * 2;
                    float2 v;
                    v.x = acc[am][an][cp * 2 + 0] + bias[n0 + cl];
                    v.y = acc[am][an][cp * 2 + 1] + bias[n0 + cl + 1];
                    *reinterpret_cast<float2*>(&dstrow[cl]) = v;
                }
            }
        }
    }
}

// ---------------------------------------------------------------------------
// FP16 MMA flash attention (FA2-style register P, ldmatrix operands).
// BQ=128, BK=64, 256 threads; warp owns 16 q-rows. smem stride 136 halves.
// ---------------------------------------------------------------------------
#define ALH 136   // halves per row (128 + 8 pad); 272B row stride

__global__ __launch_bounds__(256, 1) void attn_mma_kernel(int dummy)
{
    extern __shared__ __half sh[];
    __half* Qs = sh;                       // 128 x 136
    __half* Ks = Qs + 128 * ALH;           // 64 x 136
    __half* Vs = Ks + 64 * ALH;            // 64 x 136

    const int tid  = threadIdx.x;
    const int lane = tid & 31;
    const int w    = tid >> 5;
    const int g    = lane >> 3;
    const int l8   = lane & 7;
    const int iq   = blockIdx.x;           // q tile of 128 rows
    const int bh   = blockIdx.y;
    const int b    = bh >> 4;
    const int h    = bh & 15;

    const __half* qp = g_qh + ((size_t)bh * T_DIM + iq * 128) * HD;
    const __half* kp = g_kh + (size_t)bh * T_DIM * HD;
    const __half* vp = g_vh + (size_t)bh * T_DIM * HD;

    // load Q tile (128 x 128 halves)
#pragma unroll
    for (int r = 0; r < 8; r++) {
        int idx = tid + r * 256;
        int row = idx >> 4;
        int c   = (idx & 15) << 3;
        *reinterpret_cast<uint4*>(&Qs[row * ALH + c]) =
            *reinterpret_cast<const uint4*>(&qp[row * HD + c]);
    }
    __syncthreads();

    // preload Q fragments: 8 k-steps x 4 regs
    uint32_t qf[8][4];
#pragma unroll
    for (int ks = 0; ks < 8; ks++) {
        int row = w * 16 + (g & 1) * 8 + l8;
        int col = ks * 16 + (g >> 1) * 8;
        ldsm4(qf[ks][0], qf[ks][1], qf[ks][2], qf[ks][3],
              (uint32_t)__cvta_generic_to_shared(&Qs[row * ALH + col]));
    }

    const int r0 = lane >> 2;
    float m_i[2] = {-1e30f, -1e30f};
    float l_i[2] = {0.0f, 0.0f};
    float oacc[16][4];
#pragma unroll
    for (int na = 0; na < 16; na++)
#pragma unroll
        for (int c = 0; c < 4; c++) oacc[na][c] = 0.0f;

    const float scale = 0.08838834764831843f;   // 1/sqrt(128)
    const int jmax = 2 * iq + 1;

    for (int j = 0; j <= jmax; j++) {
        __syncthreads();
        const __half* kb = kp + (size_t)j * 64 * HD;
        const __half* vb = vp + (size_t)j * 64 * HD;
#pragma unroll
        for (int r = 0; r < 4; r++) {
            int idx = tid + r * 256;
            int row = idx >> 4;
            int c   = (idx & 15) << 3;
            *reinterpret_cast<uint4*>(&Ks[row * ALH + c]) =
                *reinterpret_cast<const uint4*>(&kb[row * HD + c]);
            *reinterpret_cast<uint4*>(&Vs[row * ALH + c]) =
                *reinterpret_cast<const uint4*>(&vb[row * HD + c]);
        }
        __syncthreads();

        // S = Q K^T : warp tile 16 x 64, K=128 (8 ksteps)
        float sacc[8][4];
#pragma unroll
        for (int na = 0; na < 8; na++)
#pragma unroll
            for (int c = 0; c < 4; c++) sacc[na][c] = 0.0f;

#pragma unroll
        for (int ks = 0; ks < 8; ks++) {
#pragma unroll
            for (int np = 0; np < 4; np++) {
                uint32_t bf[4];
                int row = np * 16 + (g >> 1) * 8 + l8;
                int col = ks * 16 + (g & 1) * 8;
                ldsm4(bf[0], bf[1], bf[2], bf[3],
                      (uint32_t)__cvta_generic_to_shared(&Ks[row * ALH + col]));
                mma_f16(sacc[2 * np],     qf[ks], &bf[0]);
                mma_f16(sacc[2 * np + 1], qf[ks], &bf[2]);
            }
        }

        // scale + causal mask
#pragma unroll
        for (int na = 0; na < 8; na++)
#pragma unroll
            for (int c = 0; c < 4; c++) sacc[na][c] *= scale;
        if (j >= 2 * iq) {
            int qrow0 = iq * 128 + w * 16 + r0;
#pragma unroll
            for (int na = 0; na < 8; na++) {
                int col = j * 64 + na * 8 + 2 * (lane & 3);
                if (col > qrow0)         sacc[na][0] = -1e30f;
                if (col + 1 > qrow0)     sacc[na][1] = -1e30f;
                if (col > qrow0 + 8)     sacc[na][2] = -1e30f;
                if (col + 1 > qrow0 + 8) sacc[na][3] = -1e30f;
            }
        }

        // online softmax
        float mt[2] = {-1e30f, -1e30f};
#pragma unroll
        for (int na = 0; na < 8; na++) {
            mt[0] = fmaxf(mt[0], fmaxf(sacc[na][0], sacc[na][1]));
            mt[1] = fmaxf(mt[1], fmaxf(sacc[na][2], sacc[na][3]));
        }
#pragma unroll
        for (int off = 1; off <= 2; off <<= 1) {
            mt[0] = fmaxf(mt[0], __shfl_xor_sync(0xffffffffu, mt[0], off));
            mt[1] = fmaxf(mt[1], __shfl_xor_sync(0xffffffffu, mt[1], off));
        }
        float mnew0 = fmaxf(m_i[0], mt[0]);
        float mnew1 = fmaxf(m_i[1], mt[1]);
        float alpha0 = __expf(m_i[0] - mnew0);
        float alpha1 = __expf(m_i[1] - mnew1);
        m_i[0] = mnew0; m_i[1] = mnew1;

        float sum0 = 0.0f, sum1 = 0.0f;
#pragma unroll
        for (int na = 0; na < 8; na++) {
            sacc[na][0] = __expf(sacc[na][0] - mnew0);
            sacc[na][1] = __expf(sacc[na][1] - mnew0);
            sacc[na][2] = __expf(sacc[na][2] - mnew1);
            sacc[na][3] = __expf(sacc[na][3] - mnew1);
            sum0 += sacc[na][0] + sacc[na][1];
            sum1 += sacc[na][2] + sacc[na][3];
        }
#pragma unroll
        for (int off = 1; off <= 2; off <<= 1) {
            sum0 += __shfl_xor_sync(0xffffffffu, sum0, off);
            sum1 += __shfl_xor_sync(0xffffffffu, sum1, off);
        }
        l_i[0] = l_i[0] * alpha0 + sum0;
        l_i[1] = l_i[1] * alpha1 + sum1;
#pragma unroll
        for (int na = 0; na < 16; na++) {
            oacc[na][0] *= alpha0; oacc[na][1] *= alpha0;
            oacc[na][2] *= alpha1; oacc[na][3] *= alpha1;
        }

        // O += P @ V  (P in registers; V via ldmatrix.trans)
        // keys: 4 chunks of 16 (kc); d: 8 groups of 16 (ng)  [bug fixed: ng<8]
#pragma unroll
        for (int kc = 0; kc < 4; kc++) {
            uint32_t pa[4];
            pa[0] = pkh(sacc[2 * kc][0],     sacc[2 * kc][1]);
            pa[1] = pkh(sacc[2 * kc][2],     sacc[2 * kc][3]);
            pa[2] = pkh(sacc[2 * kc + 1][0], sacc[2 * kc + 1][1]);
            pa[3] = pkh(sacc[2 * kc + 1][2], sacc[2 * kc + 1][3]);
#pragma unroll
            for (int ng = 0; ng < 8; ng++) {
                uint32_t vf[4];
                int row = kc * 16 + (g & 1) * 8 + l8;
                int col = ng * 16 + (g >> 1) * 8;
                ldsm4t(vf[0], vf[1], vf[2], vf[3],
                       (uint32_t)__cvta_generic_to_shared(&Vs[row * ALH + col]));
                mma_f16(oacc[2 * ng],     pa, &vf[0]);
                mma_f16(oacc[2 * ng + 1], pa, &vf[2]);
            }
        }
    }

    // finalize -> g_yh (fp16)
    float inv0 = 1.0f / l_i[0];
    float inv1 = 1.0f / l_i[1];
    int t0 = iq * 128 + w * 16 + r0;
    int t1 = t0 + 8;
    __half* dst0 = g_yh + ((size_t)(b * T_DIM + t0) * C_DIM) + h * HD;
    __half* dst1 = g_yh + ((size_t)(b * T_DIM + t1) * C_DIM) + h * HD;
#pragma unroll
    for (int na = 0; na < 16; na++) {
        int col = na * 8 + 2 * (lane & 3);
        *reinterpret_cast<uint32_t*>(&dst0[col]) =
            pkh(oacc[na][0] * inv0, oacc[na][1] * inv0);
        *reinterpret_cast<uint32_t*>(&dst1[col]) =
            pkh(oacc[na][2] * inv1, oacc[na][3] * inv1);
    }
}

// ---------------------------------------------------------------------------
extern "C" void kernel_launch(void* const* d_in, const int* in_sizes, int n_in,
                              void* d_out, int out_size)
{
    const float* x    = (const float*)d_in[0];
    const float* Wqkv = (const float*)d_in[1];
    const float* bqkv = (const float*)d_in[2];
    const float* Wout = (const float*)d_in[3];
    const float* bout = (const float*)d_in[4];

    float* y    = (float*)d_out;
    float* kout = y + YELEMS;
    float* vout = y + 2 * YELEMS;

    __half *xh, *wqkvh, *wouth, *yh;
    cudaGetSymbolAddress((void**)&xh,    g_xh);
    cudaGetSymbolAddress((void**)&wqkvh, g_wqkvh);
    cudaGetSymbolAddress((void**)&wouth, g_wouth);
    cudaGetSymbolAddress((void**)&yh,    g_yh);

    const int attn_smem = (128 + 64 + 64) * ALH * 2;   // 69632
    cudaFuncSetAttribute(attn_mma_kernel,
                         cudaFuncAttributeMaxDynamicSharedMemorySize, attn_smem);
    cudaFuncSetAttribute(mma_gemm<0>,
                         cudaFuncAttributeMaxDynamicSharedMemorySize, GEMM_SMEM);
    cudaFuncSetAttribute(mma_gemm<1>,
                         cudaFuncAttributeMaxDynamicSharedMemorySize, GEMM_SMEM);

    // 0) fp16 pre-conversion of GEMM inputs
    cvt_f16_kernel<<<2048, 256>>>((const float4*)x, (uint2*)xh, YELEMS / 4);
    cvt_f16_kernel<<<2048, 256>>>((const float4*)Wqkv, (uint2*)wqkvh,
                                  3 * C_DIM * C_DIM / 4);
    cvt_f16_kernel<<<1024, 256>>>((const float4*)Wout, (uint2*)wouth,
                                  C_DIM * C_DIM / 4);

    // 1) QKV projection (fp16 MMA, 3-stage cp.async, 2 CTA/SM) + head scatter
    mma_gemm<0><<<dim3(3 * C_DIM / BN, MTOT / BM), 256, GEMM_SMEM>>>(
        xh, wqkvh, bqkv, kout, vout);

    // 2) causal flash attention (fp16 MMA, register P) -> g_yh
    attn_mma_kernel<<<dim3(T_DIM / 128, B_DIM * NH), 256, attn_smem>>>(0);

    // 3) output projection -> y
    mma_gemm<1><<<dim3(C_DIM / BN, MTOT / BM), 256, GEMM_SMEM>>>(
        yh, wouth, bout, y, nullptr);
}